// round 13
// baseline (speedup 1.0000x reference)
#include <cuda_runtime.h>
#include <cuda_fp16.h>
#include <cstdint>

// NearestEmbed: two-pass HMMA argmin.
// Pass 1: single-combo fp16 GEMM (x0*w0, 1/3 of the old MMA count) ranks codes
//         by s = e2 - 2*xe with rigorously bounded error; candidates with
//         s <= runmin + margin are collected per pixel.
// Pass 2: exact fp32 rescore of candidates using the R1-proven chain:
//         xe = fmaf over d ascending; d2 = fadd(fadd(x2, fmul(-2,xe)), e2);
//         first-index tie-break via packed (d2,k) atomicMin.
// x2/e2 exact sequential fadd(rn(v*v)) ascending d.

#define DCH 128
#define KCODES 1024
#define HW 4096
#define BATCH 32
#define RES_ELEMS ((size_t)BATCH * DCH * HW)

#define NTHREADS 256
#define MTILE 64
#define NSTAGE 64
#define NSTAGES 16
#define CAP 32               // candidate slots per pixel

#define A_SPLIT 16384        // fp16 x0 tile: 8 chunks x 64px x 32B
#define W_SPLIT 16384        // fp16 w0 stage: 8 chunks x 64c x 32B

#define OFF_A    0
#define OFF_W    16384       // ring: 2 x 16384 = 32768 (XF f32 tile overlays here)
#define OFF_XF   16384
#define OFF_E2   49152       // 1024 f32
#define OFF_X2   53248       // 64 f32
#define OFF_MARG 53504       // 64 f32
#define OFF_WMS  53760       // 128 f32
#define OFF_BEST 54272       // 64 u64
#define OFF_CNT  54784       // 64 int
#define OFF_CAND 55040       // 64 x CAP u16 = 4096
#define SMEM_TOTAL 59136

__device__ __align__(16) unsigned char g_wsplit[NSTAGES * W_SPLIT];
__device__ __align__(16) float g_wT[KCODES * DCH];
__device__ float g_e2[KCODES];
__device__ float g_wmax[DCH];   // zero-init; atomicMax of positive float bits

// ---------------- helpers ----------------
__device__ __forceinline__ uint32_t smem_u32(const void* p) {
    uint32_t a;
    asm("{ .reg .u64 t; cvta.to.shared.u64 t, %1; cvt.u32.u64 %0, t; }" : "=r"(a) : "l"(p));
    return a;
}
__device__ __forceinline__ void cp16(uint32_t dst, const void* src) {
    asm volatile("cp.async.cg.shared.global [%0], [%1], 16;" :: "r"(dst), "l"(src) : "memory");
}
#define CP_COMMIT() asm volatile("cp.async.commit_group;" ::: "memory")
#define CP_WAIT(N)  asm volatile("cp.async.wait_group %0;" :: "n"(N) : "memory")

#define LDSM_X4(R0, R1, R2, R3, ADDR) \
    asm volatile("ldmatrix.sync.aligned.m8n8.x4.shared.b16 {%0,%1,%2,%3}, [%4];" \
        : "=r"(R0), "=r"(R1), "=r"(R2), "=r"(R3) : "r"(ADDR))

#define MMA16816(D, A0r, A1r, A2r, A3r, B0, B1) \
    asm volatile("mma.sync.aligned.m16n8k16.row.col.f32.f16.f16.f32 " \
        "{%0,%1,%2,%3}, {%4,%5,%6,%7}, {%8,%9}, {%0,%1,%2,%3};" \
        : "+f"((D)[0]), "+f"((D)[1]), "+f"((D)[2]), "+f"((D)[3]) \
        : "r"(A0r), "r"(A1r), "r"(A2r), "r"(A3r), "r"(B0), "r"(B1))

// XOR-swizzled granule offset: row p (4 rows per 128B), k-half h.
__device__ __host__ __forceinline__ uint32_t swz16(uint32_t p, uint32_t h) {
    uint32_t r = p >> 2;
    uint32_t col = (((p & 3u) * 2u + h) ^ (r & 7u));
    return r * 128u + col * 16u;
}
__device__ __forceinline__ uint4 pack8(const unsigned short* s) {
    uint4 v;
    v.x = (uint32_t)s[0] | ((uint32_t)s[1] << 16);
    v.y = (uint32_t)s[2] | ((uint32_t)s[3] << 16);
    v.z = (uint32_t)s[4] | ((uint32_t)s[5] << 16);
    v.w = (uint32_t)s[6] | ((uint32_t)s[7] << 16);
    return v;
}

// ---------------- prep: e2 + wT + wmax + fp16 w0 (scaled x1024) ----------------
__global__ void convert_w_kernel(const float* __restrict__ w) {
    __shared__ float wred[DCH];
    const int nt = blockIdx.x;
    const int c = threadIdx.x;          // 0..63
    const int k = nt * NSTAGE + c;
    for (int i = c; i < DCH; i += NSTAGE) wred[i] = 0.0f;
    __syncthreads();
    float e2 = 0.0f;
    for (int g = 0; g < 16; ++g) {
        unsigned short s0[8];
#pragma unroll
        for (int j = 0; j < 8; ++j) {
            int d = g * 8 + j;
            float v = w[(size_t)d * KCODES + k];
            e2 = __fadd_rn(e2, __fmul_rn(v, v));
            g_wT[(size_t)k * DCH + d] = v;
            atomicMax((int*)&wred[d], __float_as_int(fabsf(v)));
            s0[j] = __half_as_ushort(__float2half_rn(v * 1024.0f));
        }
        *(uint4*)(g_wsplit + (size_t)nt * W_SPLIT + (size_t)(g >> 1) * 2048
                  + swz16((uint32_t)c, (uint32_t)(g & 1))) = pack8(s0);
    }
    g_e2[k] = e2;
    __syncthreads();
    for (int i = c; i < DCH; i += NSTAGE)
        atomicMax((int*)&g_wmax[i], __float_as_int(wred[i]));
}

// ---------------- main ----------------
__global__ __launch_bounds__(NTHREADS, 2)
void nearest_embed_2pass_kernel(const float* __restrict__ x,
                                const float* __restrict__ w,
                                float* __restrict__ out,
                                int write_amin) {
    extern __shared__ char smem[];
    const uint32_t su = smem_u32(smem);
    const int tid = threadIdx.x;
    const int blk = blockIdx.x;
    const int b = blk >> 6;
    const int hw0 = (blk & 63) * MTILE;

    float* e2s = (float*)(smem + OFF_E2);
    float* x2s = (float*)(smem + OFF_X2);
    float* margins = (float*)(smem + OFF_MARG);
    float* wms = (float*)(smem + OFF_WMS);
    unsigned long long* best = (unsigned long long*)(smem + OFF_BEST);
    int* cnt = (int*)(smem + OFF_CNT);
    unsigned short* cands = (unsigned short*)(smem + OFF_CAND);

    if (tid < MTILE) { best[tid] = 0xFFFFFFFFFFFFFFFFull; cnt[tid] = 0; }
    for (int i = tid; i < KCODES; i += NTHREADS) e2s[i] = g_e2[i];
    if (tid < DCH) wms[tid] = g_wmax[tid];

    // ---- stage x f32 tile [128d][64px] ----
    const float* xbase = x + ((size_t)b * DCH) * HW + hw0;
    for (int t = tid; t < DCH * 16; t += NTHREADS) {
        int d = t >> 4, q = t & 15;
        cp16(su + OFF_XF + (uint32_t)(d * 256 + q * 16),
             xbase + (size_t)d * HW + q * 4);
    }
    CP_COMMIT();
    CP_WAIT(0);
    __syncthreads();

    // ---- x2 (exact) + per-pixel margin ----
    const float* xf = (const float*)(smem + OFF_XF);
    if (tid < MTILE) {
        float a = 0.0f, m = 0.0f;
        for (int d = 0; d < DCH; ++d) {
            float v = xf[d * MTILE + tid];
            a = __fadd_rn(a, __fmul_rn(v, v));
            m = fmaf(fabsf(v), wms[d], m);
        }
        x2s[tid] = a;
        margins[tid] = m * 0.0022f + 1.5e-4f;   // >= 2*eps + fp32-rounding window
    }

    // ---- convert x -> single fp16 tile (swizzled) ----
    {
        const int px = tid & 63;
        const int quarter = tid >> 6;
        for (int g = quarter * 4; g < quarter * 4 + 4; ++g) {
            unsigned short s0[8];
#pragma unroll
            for (int j = 0; j < 8; ++j)
                s0[j] = __half_as_ushort(__float2half_rn(xf[(g * 8 + j) * MTILE + px]));
            *(uint4*)(smem + OFF_A + (g >> 1) * 2048
                      + swz16((uint32_t)px, (uint32_t)(g & 1))) = pack8(s0);
        }
    }
    __syncthreads();   // A ready; XF area (= W ring) reusable

    // ---- prefetch w stage 0 ----
    for (int t = tid; t < W_SPLIT / 16; t += NTHREADS)
        cp16(su + OFF_W + (uint32_t)(t * 16), g_wsplit + (size_t)t * 16);
    CP_COMMIT();

    // ---- fragment addressing ----
    const int lane = tid & 31;
    const int warp = tid >> 5;
    const int pg = warp >> 1;
    const int chalf = warp & 1;
    const int px0 = pg * 16;
    const int pxA = px0 + (lane >> 2);
    const int pxB = pxA + 8;

    const uint32_t ap = (uint32_t)(px0 + (lane & 7) + ((lane >> 3) & 1) * 8);
    const uint32_t ah = (uint32_t)(lane >> 4);
    const uint32_t aoff = swz16(ap, ah);
    const uint32_t bc = (uint32_t)((lane & 7) + ((lane >> 4) & 1) * 8);
    const uint32_t bh = (uint32_t)((lane >> 3) & 1);
    uint32_t boff[2];
#pragma unroll
    for (int ct = 0; ct < 2; ++ct)
        boff[ct] = swz16((uint32_t)(chalf * 32 + ct * 16) + bc, bh);

    // ---- hoist A fragments (32 regs, compile-time indices) ----
    uint32_t Ar[32];
#pragma unroll
    for (int ch = 0; ch < 8; ++ch)
        LDSM_X4(Ar[ch * 4 + 0], Ar[ch * 4 + 1], Ar[ch * 4 + 2], Ar[ch * 4 + 3],
                su + OFF_A + ch * 2048 + aoff);

    const float MA = margins[pxA];
    const float MB = margins[pxB];

    float acc[4][4];
#pragma unroll
    for (int t = 0; t < 4; ++t)
#pragma unroll
        for (int q = 0; q < 4; ++q) acc[t][q] = 0.0f;

    float bdA = __int_as_float(0x7F800000), bdB = bdA;

    // ================= PASS 1 =================
    for (int nt = 0; nt < NSTAGES; ++nt) {
        CP_WAIT(0);
        __syncthreads();

        if (nt + 1 < NSTAGES) {
            const unsigned char* src = g_wsplit + (size_t)(nt + 1) * W_SPLIT;
            const uint32_t dst = su + OFF_W + ((nt + 1) & 1) * W_SPLIT;
            for (int t = tid; t < W_SPLIT / 16; t += NTHREADS)
                cp16(dst + (uint32_t)(t * 16), src + (size_t)t * 16);
            CP_COMMIT();
        }

        const uint32_t wb = su + OFF_W + (nt & 1) * W_SPLIT;

#pragma unroll
        for (int ch = 0; ch < 8; ++ch) {
            uint32_t p0, p1, p2, p3, r0, r1, r2, r3;
            LDSM_X4(p0, p1, p2, p3, wb + ch * 2048 + boff[0]);
            LDSM_X4(r0, r1, r2, r3, wb + ch * 2048 + boff[1]);
            MMA16816(acc[0], Ar[ch * 4 + 0], Ar[ch * 4 + 1], Ar[ch * 4 + 2], Ar[ch * 4 + 3], p0, p1);
            MMA16816(acc[1], Ar[ch * 4 + 0], Ar[ch * 4 + 1], Ar[ch * 4 + 2], Ar[ch * 4 + 3], p2, p3);
            MMA16816(acc[2], Ar[ch * 4 + 0], Ar[ch * 4 + 1], Ar[ch * 4 + 2], Ar[ch * 4 + 3], r0, r1);
            MMA16816(acc[3], Ar[ch * 4 + 0], Ar[ch * 4 + 1], Ar[ch * 4 + 2], Ar[ch * 4 + 3], r2, r3);
        }

        // ---- epilogue: s = e2 - 2*xe (acc holds 1024*xe); min then push ----
        const int kq = nt * NSTAGE + chalf * 32 + (lane & 3) * 2;
#pragma unroll
        for (int t = 0; t < 4; ++t)
#pragma unroll
            for (int q = 0; q < 4; ++q) {
                const int kk = kq + t * 8 + (q & 1);
                float s = __fadd_rn(e2s[kk], __fmul_rn(-0.001953125f, acc[t][q]));
                acc[t][q] = s;
                if (q < 2) { if (s < bdA) bdA = s; }
                else       { if (s < bdB) bdB = s; }
            }
#pragma unroll
        for (int t = 0; t < 4; ++t)
#pragma unroll
            for (int q = 0; q < 4; ++q) {
                const int kk = kq + t * 8 + (q & 1);
                const float thr = (q < 2) ? (bdA + MA) : (bdB + MB);
                const int px = (q < 2) ? pxA : pxB;
                if (acc[t][q] <= thr) {
                    int slot = atomicAdd(&cnt[px], 1);
                    if (slot < CAP) cands[px * CAP + slot] = (unsigned short)kk;
                }
                acc[t][q] = 0.0f;
            }
    }

    // ================= PASS 2: exact rescore =================
    __syncthreads();
    // reload x f32 tile (W ring is done)
    for (int t = tid; t < DCH * 16; t += NTHREADS) {
        int d = t >> 4, q = t & 15;
        cp16(su + OFF_XF + (uint32_t)(d * 256 + q * 16),
             xbase + (size_t)d * HW + q * 4);
    }
    CP_COMMIT();
    CP_WAIT(0);
    __syncthreads();

    {
        const float* xf2 = (const float*)(smem + OFF_XF);
        const int px = tid >> 2, th = tid & 3;
        const int cv = cnt[px];
        const float x2v = x2s[px];
        if (cv <= CAP) {
            for (int i = th; i < cv; i += 4) {
                const int k = cands[px * CAP + i];
                const float* wrow = g_wT + (size_t)k * DCH;
                float xe = 0.0f;
#pragma unroll 8
                for (int d = 0; d < DCH; ++d)
                    xe = fmaf(xf2[d * MTILE + px], __ldg(wrow + d), xe);
                float d2 = __fadd_rn(__fadd_rn(x2v, __fmul_rn(-2.0f, xe)), e2s[k]);
                unsigned long long pk =
                    ((unsigned long long)__float_as_uint(d2) << 32) | (unsigned)k;
                atomicMin(&best[px], pk);
            }
        } else {   // overflow fallback: exact scan of all codes (rare)
            for (int k = th; k < KCODES; k += 4) {
                const float* wrow = g_wT + (size_t)k * DCH;
                float xe = 0.0f;
#pragma unroll 8
                for (int d = 0; d < DCH; ++d)
                    xe = fmaf(xf2[d * MTILE + px], __ldg(wrow + d), xe);
                float d2 = __fadd_rn(__fadd_rn(x2v, __fmul_rn(-2.0f, xe)), e2s[k]);
                unsigned long long pk =
                    ((unsigned long long)__float_as_uint(d2) << 32) | (unsigned)k;
                atomicMin(&best[px], pk);
            }
        }
    }
    __syncthreads();

    // ---- outputs: gather codebook rows + argmin ----
    const size_t obase = ((size_t)b * DCH) * HW + hw0;
    for (int t = tid; t < DCH * MTILE; t += NTHREADS) {
        int d = t >> 6;
        int px = t & 63;
        unsigned k = (unsigned)(best[px] & 0xFFFFFFFFu);
        out[obase + (size_t)d * HW + px] = w[(size_t)d * KCODES + k];
    }
    if (write_amin && tid < MTILE) {
        unsigned k = (unsigned)(best[tid] & 0xFFFFFFFFu);
        out[RES_ELEMS + (size_t)b * HW + hw0 + tid] = (float)k;
    }
}

extern "C" void kernel_launch(void* const* d_in, const int* in_sizes, int n_in,
                              void* d_out, int out_size) {
    const float* x = (const float*)d_in[0];
    const float* w = (const float*)d_in[1];
    float* out = (float*)d_out;
    const int write_amin = ((size_t)out_size > RES_ELEMS) ? 1 : 0;

    cudaFuncSetAttribute(nearest_embed_2pass_kernel,
                         cudaFuncAttributeMaxDynamicSharedMemorySize, SMEM_TOTAL);

    convert_w_kernel<<<NSTAGES, NSTAGE>>>(w);
    nearest_embed_2pass_kernel<<<(BATCH * HW) / MTILE, NTHREADS, SMEM_TOTAL>>>(
        x, w, out, write_amin);
}

// round 14
// speedup vs baseline: 20.6496x; 20.6496x over previous
#include <cuda_runtime.h>
#include <cuda_fp16.h>
#include <cstdint>

// NearestEmbed: two-pass HMMA argmin.
// Pass 1: single-combo fp16 GEMM ranks codes by s = e2 - 2*xe; per-pixel
//         SHARED running min (atomicMin on positive-offset float bits);
//         candidates with s <= runmin + margin collected (margin is a proven
//         superset bound: 2*fp16-product error + fp32 d2-rounding window).
// Pass 2: exact fp32 rescore of candidates (R13-validated chain, == reference):
//         xe = fmaf over d ascending; d2 = fadd(fadd(x2, fmul(-2,xe)), e2);
//         first-index tie-break via packed (d2,k) atomicMin.
// x2/e2 exact sequential fadd(rn(v*v)) ascending d.

#define DCH 128
#define KCODES 1024
#define HW 4096
#define BATCH 32
#define RES_ELEMS ((size_t)BATCH * DCH * HW)

#define NTHREADS 256
#define MTILE 64
#define NSTAGE 64
#define NSTAGES 16
#define CAP 32

#define A_SPLIT 16384
#define W_SPLIT 16384

#define OFF_A    0
#define OFF_W    16384       // ring: 2 x 16384 (XF f32 tile overlays here)
#define OFF_XF   16384
#define OFF_E2   49152       // 1024 f32
#define OFF_X2   53248       // 64 f32
#define OFF_MARG 53504       // 64 f32
#define OFF_WMS  53760       // 128 f32
#define OFF_SMIN 54272       // 64 int (s+4 float bits)
#define OFF_BEST 54528       // 64 u64
#define OFF_CNT  55040       // 64 int
#define OFF_CAND 55296       // 64 x CAP u16 = 4096
#define SMEM_TOTAL 59392

__device__ __align__(16) unsigned char g_wsplit[NSTAGES * W_SPLIT];
__device__ __align__(16) float g_wT[KCODES * DCH];
__device__ float g_e2[KCODES];
__device__ float g_wmax[DCH];

// ---------------- helpers ----------------
__device__ __forceinline__ uint32_t smem_u32(const void* p) {
    uint32_t a;
    asm("{ .reg .u64 t; cvta.to.shared.u64 t, %1; cvt.u32.u64 %0, t; }" : "=r"(a) : "l"(p));
    return a;
}
__device__ __forceinline__ void cp16(uint32_t dst, const void* src) {
    asm volatile("cp.async.cg.shared.global [%0], [%1], 16;" :: "r"(dst), "l"(src) : "memory");
}
#define CP_COMMIT() asm volatile("cp.async.commit_group;" ::: "memory")
#define CP_WAIT(N)  asm volatile("cp.async.wait_group %0;" :: "n"(N) : "memory")

#define LDSM_X4(R0, R1, R2, R3, ADDR) \
    asm volatile("ldmatrix.sync.aligned.m8n8.x4.shared.b16 {%0,%1,%2,%3}, [%4];" \
        : "=r"(R0), "=r"(R1), "=r"(R2), "=r"(R3) : "r"(ADDR))

#define MMA16816(D, A0r, A1r, A2r, A3r, B0, B1) \
    asm volatile("mma.sync.aligned.m16n8k16.row.col.f32.f16.f16.f32 " \
        "{%0,%1,%2,%3}, {%4,%5,%6,%7}, {%8,%9}, {%0,%1,%2,%3};" \
        : "+f"((D)[0]), "+f"((D)[1]), "+f"((D)[2]), "+f"((D)[3]) \
        : "r"(A0r), "r"(A1r), "r"(A2r), "r"(A3r), "r"(B0), "r"(B1))

__device__ __host__ __forceinline__ uint32_t swz16(uint32_t p, uint32_t h) {
    uint32_t r = p >> 2;
    uint32_t col = (((p & 3u) * 2u + h) ^ (r & 7u));
    return r * 128u + col * 16u;
}
__device__ __forceinline__ uint4 pack8(const unsigned short* s) {
    uint4 v;
    v.x = (uint32_t)s[0] | ((uint32_t)s[1] << 16);
    v.y = (uint32_t)s[2] | ((uint32_t)s[3] << 16);
    v.z = (uint32_t)s[4] | ((uint32_t)s[5] << 16);
    v.w = (uint32_t)s[6] | ((uint32_t)s[7] << 16);
    return v;
}

// ---------------- prep: e2 + wT + wmax + fp16 w (scaled x1024) ----------------
__global__ void convert_w_kernel(const float* __restrict__ w) {
    __shared__ float wred[DCH];
    const int nt = blockIdx.x;
    const int c = threadIdx.x;          // 0..63
    const int k = nt * NSTAGE + c;
    for (int i = c; i < DCH; i += NSTAGE) wred[i] = 0.0f;
    __syncthreads();
    float e2 = 0.0f;
    for (int g = 0; g < 16; ++g) {
        unsigned short s0[8];
#pragma unroll
        for (int j = 0; j < 8; ++j) {
            int d = g * 8 + j;
            float v = w[(size_t)d * KCODES + k];
            e2 = __fadd_rn(e2, __fmul_rn(v, v));
            g_wT[(size_t)k * DCH + d] = v;
            atomicMax((int*)&wred[d], __float_as_int(fabsf(v)));
            s0[j] = __half_as_ushort(__float2half_rn(v * 1024.0f));
        }
        *(uint4*)(g_wsplit + (size_t)nt * W_SPLIT + (size_t)(g >> 1) * 2048
                  + swz16((uint32_t)c, (uint32_t)(g & 1))) = pack8(s0);
    }
    g_e2[k] = e2;
    __syncthreads();
    for (int i = c; i < DCH; i += NSTAGE)
        atomicMax((int*)&g_wmax[i], __float_as_int(wred[i]));
}

// ---------------- main ----------------
__global__ __launch_bounds__(NTHREADS, 2)
void nearest_embed_2pass_kernel(const float* __restrict__ x,
                                const float* __restrict__ w,
                                float* __restrict__ out,
                                int write_amin) {
    extern __shared__ char smem[];
    const uint32_t su = smem_u32(smem);
    const int tid = threadIdx.x;
    const int blk = blockIdx.x;
    const int b = blk >> 6;
    const int hw0 = (blk & 63) * MTILE;

    float* e2s = (float*)(smem + OFF_E2);
    float* x2s = (float*)(smem + OFF_X2);
    float* margins = (float*)(smem + OFF_MARG);
    float* wms = (float*)(smem + OFF_WMS);
    int* smin = (int*)(smem + OFF_SMIN);
    unsigned long long* best = (unsigned long long*)(smem + OFF_BEST);
    int* cnt = (int*)(smem + OFF_CNT);
    unsigned short* cands = (unsigned short*)(smem + OFF_CAND);

    if (tid < MTILE) {
        best[tid] = 0xFFFFFFFFFFFFFFFFull;
        cnt[tid] = 0;
        smin[tid] = 0x7F800000;            // +inf in offset domain
    }
    for (int i = tid; i < KCODES; i += NTHREADS) e2s[i] = g_e2[i];
    if (tid < DCH) wms[tid] = g_wmax[tid];

    // ---- stage x f32 tile [128d][64px] ----
    const float* xbase = x + ((size_t)b * DCH) * HW + hw0;
    for (int t = tid; t < DCH * 16; t += NTHREADS) {
        int d = t >> 4, q = t & 15;
        cp16(su + OFF_XF + (uint32_t)(d * 256 + q * 16),
             xbase + (size_t)d * HW + q * 4);
    }
    CP_COMMIT();
    CP_WAIT(0);
    __syncthreads();

    // ---- x2 (exact) + per-pixel margin (proven superset bound) ----
    const float* xf = (const float*)(smem + OFF_XF);
    if (tid < MTILE) {
        float a = 0.0f, m = 0.0f;
        for (int d = 0; d < DCH; ++d) {
            float v = xf[d * MTILE + tid];
            a = __fadd_rn(a, __fmul_rn(v, v));
            m = fmaf(fabsf(v), wms[d], m);
        }
        x2s[tid] = a;
        margins[tid] = m * 0.0045f + 2.0e-4f;   // 2*err_s + d2-rounding window
    }

    // ---- convert x -> single fp16 tile (swizzled) ----
    {
        const int px = tid & 63;
        const int quarter = tid >> 6;
        for (int g = quarter * 4; g < quarter * 4 + 4; ++g) {
            unsigned short s0[8];
#pragma unroll
            for (int j = 0; j < 8; ++j)
                s0[j] = __half_as_ushort(__float2half_rn(xf[(g * 8 + j) * MTILE + px]));
            *(uint4*)(smem + OFF_A + (g >> 1) * 2048
                      + swz16((uint32_t)px, (uint32_t)(g & 1))) = pack8(s0);
        }
    }
    __syncthreads();   // A ready; XF area (= W ring) reusable

    // ---- prefetch w stage 0 ----
    for (int t = tid; t < W_SPLIT / 16; t += NTHREADS)
        cp16(su + OFF_W + (uint32_t)(t * 16), g_wsplit + (size_t)t * 16);
    CP_COMMIT();

    // ---- fragment addressing ----
    const int lane = tid & 31;
    const int warp = tid >> 5;
    const int pg = warp >> 1;
    const int chalf = warp & 1;
    const int px0 = pg * 16;
    const int pxA = px0 + (lane >> 2);
    const int pxB = pxA + 8;

    const uint32_t ap = (uint32_t)(px0 + (lane & 7) + ((lane >> 3) & 1) * 8);
    const uint32_t ah = (uint32_t)(lane >> 4);
    const uint32_t aoff = swz16(ap, ah);
    const uint32_t bc = (uint32_t)((lane & 7) + ((lane >> 4) & 1) * 8);
    const uint32_t bh = (uint32_t)((lane >> 3) & 1);
    uint32_t boff[2];
#pragma unroll
    for (int ct = 0; ct < 2; ++ct)
        boff[ct] = swz16((uint32_t)(chalf * 32 + ct * 16) + bc, bh);

    // ---- hoist A fragments (32 regs, compile-time indices) ----
    uint32_t Ar[32];
#pragma unroll
    for (int ch = 0; ch < 8; ++ch)
        LDSM_X4(Ar[ch * 4 + 0], Ar[ch * 4 + 1], Ar[ch * 4 + 2], Ar[ch * 4 + 3],
                su + OFF_A + ch * 2048 + aoff);

    const float MA = margins[pxA];
    const float MB = margins[pxB];

    float acc[4][4];
#pragma unroll
    for (int t = 0; t < 4; ++t)
#pragma unroll
        for (int q = 0; q < 4; ++q) acc[t][q] = 0.0f;

    // ================= PASS 1 =================
    for (int nt = 0; nt < NSTAGES; ++nt) {
        CP_WAIT(0);
        __syncthreads();

        if (nt + 1 < NSTAGES) {
            const unsigned char* src = g_wsplit + (size_t)(nt + 1) * W_SPLIT;
            const uint32_t dst = su + OFF_W + ((nt + 1) & 1) * W_SPLIT;
            for (int t = tid; t < W_SPLIT / 16; t += NTHREADS)
                cp16(dst + (uint32_t)(t * 16), src + (size_t)t * 16);
            CP_COMMIT();
        }

        const uint32_t wb = su + OFF_W + (nt & 1) * W_SPLIT;

#pragma unroll
        for (int ch = 0; ch < 8; ++ch) {
            uint32_t p0, p1, p2, p3, r0, r1, r2, r3;
            LDSM_X4(p0, p1, p2, p3, wb + ch * 2048 + boff[0]);
            LDSM_X4(r0, r1, r2, r3, wb + ch * 2048 + boff[1]);
            MMA16816(acc[0], Ar[ch * 4 + 0], Ar[ch * 4 + 1], Ar[ch * 4 + 2], Ar[ch * 4 + 3], p0, p1);
            MMA16816(acc[1], Ar[ch * 4 + 0], Ar[ch * 4 + 1], Ar[ch * 4 + 2], Ar[ch * 4 + 3], p2, p3);
            MMA16816(acc[2], Ar[ch * 4 + 0], Ar[ch * 4 + 1], Ar[ch * 4 + 2], Ar[ch * 4 + 3], r0, r1);
            MMA16816(acc[3], Ar[ch * 4 + 0], Ar[ch * 4 + 1], Ar[ch * 4 + 2], Ar[ch * 4 + 3], r2, r3);
        }

        // ---- phase 1: s = e2 - 2*xe (acc holds 1024*xe, -2/1024 exact);
        //               update SHARED per-pixel running min (offset domain) ----
        float lminA = __int_as_float(0x7F800000), lminB = lminA;
        const int kq = nt * NSTAGE + chalf * 32 + (lane & 3) * 2;
#pragma unroll
        for (int t = 0; t < 4; ++t)
#pragma unroll
            for (int q = 0; q < 4; ++q) {
                const int kk = kq + t * 8 + (q & 1);
                float s = __fadd_rn(e2s[kk], __fmul_rn(-0.001953125f, acc[t][q]));
                acc[t][q] = s;
                if (q < 2) { if (s < lminA) lminA = s; }
                else       { if (s < lminB) lminB = s; }
            }
        atomicMin(&smin[pxA], __float_as_int(lminA + 4.0f));   // s+4 > 0 always
        atomicMin(&smin[pxB], __float_as_int(lminB + 4.0f));
        __syncthreads();   // running min now global across the pixel's threads

        // ---- phase 2: push candidates vs global running min + margin ----
        const float thrA = __int_as_float(smin[pxA]) - 4.0f + MA;
        const float thrB = __int_as_float(smin[pxB]) - 4.0f + MB;
#pragma unroll
        for (int t = 0; t < 4; ++t)
#pragma unroll
            for (int q = 0; q < 4; ++q) {
                const int kk = kq + t * 8 + (q & 1);
                const float thr = (q < 2) ? thrA : thrB;
                const int px = (q < 2) ? pxA : pxB;
                if (acc[t][q] <= thr) {
                    int slot = atomicAdd(&cnt[px], 1);
                    if (slot < CAP) cands[px * CAP + slot] = (unsigned short)kk;
                }
                acc[t][q] = 0.0f;
            }
    }

    // ================= PASS 2: exact rescore =================
    __syncthreads();
    for (int t = tid; t < DCH * 16; t += NTHREADS) {   // reload x f32 tile
        int d = t >> 4, q = t & 15;
        cp16(su + OFF_XF + (uint32_t)(d * 256 + q * 16),
             xbase + (size_t)d * HW + q * 4);
    }
    CP_COMMIT();
    CP_WAIT(0);
    __syncthreads();

    {
        const float* xf2 = (const float*)(smem + OFF_XF);
        const int px = tid >> 2, th = tid & 3;
        const int cv = cnt[px];
        const float x2v = x2s[px];
        const int lim = (cv <= CAP) ? cv : KCODES;
        for (int i = th; i < lim; i += 4) {
            const int k = (cv <= CAP) ? cands[px * CAP + i] : i;
            const float* wrow = g_wT + (size_t)k * DCH;
            float xe = 0.0f;
#pragma unroll 8
            for (int d = 0; d < DCH; ++d)
                xe = fmaf(xf2[d * MTILE + px], __ldg(wrow + d), xe);
            float d2 = __fadd_rn(__fadd_rn(x2v, __fmul_rn(-2.0f, xe)), e2s[k]);
            unsigned long long pk =
                ((unsigned long long)__float_as_uint(d2) << 32) | (unsigned)k;
            atomicMin(&best[px], pk);
        }
    }
    __syncthreads();

    // ---- outputs: gather codebook rows + argmin ----
    const size_t obase = ((size_t)b * DCH) * HW + hw0;
    for (int t = tid; t < DCH * MTILE; t += NTHREADS) {
        int d = t >> 6;
        int px = t & 63;
        unsigned k = (unsigned)(best[px] & 0xFFFFFFFFu);
        out[obase + (size_t)d * HW + px] = w[(size_t)d * KCODES + k];
    }
    if (write_amin && tid < MTILE) {
        unsigned k = (unsigned)(best[tid] & 0xFFFFFFFFu);
        out[RES_ELEMS + (size_t)b * HW + hw0 + tid] = (float)k;
    }
}

extern "C" void kernel_launch(void* const* d_in, const int* in_sizes, int n_in,
                              void* d_out, int out_size) {
    const float* x = (const float*)d_in[0];
    const float* w = (const float*)d_in[1];
    float* out = (float*)d_out;
    const int write_amin = ((size_t)out_size > RES_ELEMS) ? 1 : 0;

    cudaFuncSetAttribute(nearest_embed_2pass_kernel,
                         cudaFuncAttributeMaxDynamicSharedMemorySize, SMEM_TOTAL);

    convert_w_kernel<<<NSTAGES, NSTAGE>>>(w);
    nearest_embed_2pass_kernel<<<(BATCH * HW) / MTILE, NTHREADS, SMEM_TOTAL>>>(
        x, w, out, write_amin);
}